// round 11
// baseline (speedup 1.0000x reference)
#include <cuda_runtime.h>

// Shapes (fixed)
#define Bn 16
#define In 32
#define Cn 8
#define Jn 10
#define Dn 16
#define Xn 576    // D*H*W
#define XT 192    // third handled per CTA
#define NT 192    // threads per CTA (6 warps)
#define HWn 36
#define EPSf 1e-7f
#define GRIDG (Bn*Jn*3)   // 480 CTAs; 4/SM co-resident (84 regs, 107KB smem/SM)

// Cross-CTA comm scratch, parity double-buffered (WAR safety across the single
// per-iteration grid barrier). Entry = bj*3 + third. For batch b the 30 norm
// entries are contiguous: [b*30 .. b*30+29].
__device__ float    g_nPart[2][GRIDG];
__device__ float    g_aPart[2][GRIDG * In];   // [entry][i], i contiguous (128B rows)
__device__ unsigned g_cnt;
__device__ unsigned g_gen;

__device__ __forceinline__ float squash_k(float n) {
    float n2 = n * n;
    return (n2 / (1.f + n2)) / (n + EPSf);
}

// Grid barrier. All 480 CTAs co-resident (480 <= 148*4; launch_bounds 4/SM).
__device__ __forceinline__ void gridBarrier() {
    __threadfence();
    __syncthreads();
    if (threadIdx.x == 0) {
        unsigned g0 = *(volatile unsigned*)&g_gen;
        unsigned a = atomicAdd(&g_cnt, 1u);
        if (a == GRIDG - 1) {
            atomicExch(&g_cnt, 0u);
            __threadfence();
            atomicAdd(&g_gen, 1u);
        } else {
            while (*(volatile unsigned*)&g_gen == g0) { }
        }
        __threadfence();
    }
    __syncthreads();
}

// Block sum over 192 threads (6 warps); valid on thread 0.
__device__ __forceinline__ float blockReduceSum192(float v) {
    __shared__ float red[6];
    int lane = threadIdx.x & 31, w = threadIdx.x >> 5;
    #pragma unroll
    for (int o = 16; o > 0; o >>= 1) v += __shfl_down_sync(0xffffffffu, v, o);
    if (lane == 0) red[w] = v;
    __syncthreads();
    float s = 0.f;
    if (threadIdx.x == 0) {
        #pragma unroll
        for (int k = 0; k < 6; k++) s += red[k];
    }
    return s;
}

__global__ void __launch_bounds__(NT, 4) routing_all(
    const float* __restrict__ u, const float* __restrict__ bias,
    float* __restrict__ out)
{
    __shared__ __align__(16) float Us[In][XT];  // 24,576 B resident U tile
    __shared__ float ss[XT];
    __shared__ float sb[In * Jn];     // routing logits (identical in all CTAs)
    __shared__ float cs[In];          // coupling coeffs for this CTA's j
    __shared__ float kb_sh[Bn];
    int bj = blockIdx.x / 3, third = blockIdx.x % 3;
    int b = bj / Jn, j = bj % Jn;
    int x = threadIdx.x;
    int xg = third * XT + x;
    int w = x >> 5, lane = x & 31;
    float biasv = bias[j * Dn + xg / HWn];

    for (int t = x; t < In * Jn; t += NT) sb[t] = 0.f;

    // ---- Load phase: Us[i][x] = sum_c u_hat[b,i,c,j,xg]. 94 MB streamed once.
    // 4 i-groups x 48 float4-cols; 24 warps/SM -> expect ~6.5 TB/s.
    {
        int t4 = x % 48, g = x / 48;
        int xq = third * XT + t4 * 4;
        const float* base = u + (size_t)b * In * Cn * Jn * Xn + (size_t)j * Xn + xq;
        #pragma unroll 1
        for (int ii = 0; ii < 8; ii++) {
            int i = g * 8 + ii;
            const float4* p = (const float4*)(base + (size_t)i * Cn * Jn * Xn);
            float4 a0 = __ldcs(p);
            float4 a1 = __ldcs(p + 1 * (Jn * Xn / 4));
            float4 a2 = __ldcs(p + 2 * (Jn * Xn / 4));
            float4 a3 = __ldcs(p + 3 * (Jn * Xn / 4));
            float4 a4 = __ldcs(p + 4 * (Jn * Xn / 4));
            float4 a5 = __ldcs(p + 5 * (Jn * Xn / 4));
            float4 a6 = __ldcs(p + 6 * (Jn * Xn / 4));
            float4 a7 = __ldcs(p + 7 * (Jn * Xn / 4));
            float4 acc;
            acc.x = ((a0.x + a1.x) + (a2.x + a3.x)) + ((a4.x + a5.x) + (a6.x + a7.x));
            acc.y = ((a0.y + a1.y) + (a2.y + a3.y)) + ((a4.y + a5.y) + (a6.y + a7.y));
            acc.z = ((a0.z + a1.z) + (a2.z + a3.z)) + ((a4.z + a5.z) + (a6.z + a7.z));
            acc.w = ((a0.w + a1.w) + (a2.w + a3.w)) + ((a4.w + a5.w) + (a6.w + a7.w));
            *(float4*)&Us[i][t4 * 4] = acc;
        }
    }
    __syncthreads();

    float s = 0.f;
    #pragma unroll 1
    for (int iter = 0; iter < 3; iter++) {
        int pb = iter & 1;

        // ---- routing update from previous iteration's partials (iter > 0).
        // Coalesced: lane = i, one 128B line per entry row.
        if (iter > 0) {
            int prev = (iter - 1) & 1;
            if (x < Bn) {
                float nn = 0.f;
                #pragma unroll
                for (int t = 0; t < Jn * 3; t++) nn += __ldcg(&g_nPart[prev][x * Jn * 3 + t]);
                kb_sh[x] = squash_k(nn);
            }
            __syncthreads();
            for (int jj = w; jj < Jn; jj += 6) {
                float a = 0.f;
                #pragma unroll
                for (int bb = 0; bb < Bn; bb++) {
                    int e0 = (bb * Jn + jj) * 3;
                    float p0 = __ldcg(&g_aPart[prev][(size_t)(e0 + 0) * In + lane]);
                    float p1 = __ldcg(&g_aPart[prev][(size_t)(e0 + 1) * In + lane]);
                    float p2 = __ldcg(&g_aPart[prev][(size_t)(e0 + 2) * In + lane]);
                    a += kb_sh[bb] * ((p0 + p1) + p2);
                }
                sb[lane * Jn + jj] += a;      // b_ij += agreement
            }
            __syncthreads();
            if (x < In) {
                float mx = -1e30f;
                #pragma unroll
                for (int jj = 0; jj < Jn; jj++) mx = fmaxf(mx, sb[x * Jn + jj]);
                float den = 0.f;
                #pragma unroll
                for (int jj = 0; jj < Jn; jj++) den += expf(sb[x * Jn + jj] - mx);
                cs[x] = expf(sb[x * Jn + j] - mx) / den;
            }
            __syncthreads();
        }

        // ---- s_j for this (b,j,third)
        if (iter == 0) {
            float acc = 0.f;
            #pragma unroll
            for (int i = 0; i < In; i++) acc += Us[i][x];
            s = acc * (1.0f / Jn) + biasv;    // softmax(0) = 1/J exactly
        } else {
            float acc = 0.f;
            #pragma unroll
            for (int i = 0; i < In; i++) acc += cs[i] * Us[i][x];
            s = acc + biasv;
        }
        // ---- L1-norm partial
        float n = blockReduceSum192(fabsf(s));
        if (x == 0) g_nPart[pb][blockIdx.x] = n;

        if (iter == 2) break;                 // final agreement is dead

        ss[x] = s;
        __syncthreads();
        // ---- unscaled agreement partials: aU[i] = sum_x Us[i][x]*ss[x]
        for (int i = w; i < In; i += 6) {
            float a = 0.f;
            #pragma unroll
            for (int xx = lane; xx < XT; xx += 32) a += Us[i][xx] * ss[xx];
            #pragma unroll
            for (int o = 16; o > 0; o >>= 1) a += __shfl_down_sync(0xffffffffu, a, o);
            if (lane == 0) g_aPart[pb][(size_t)blockIdx.x * In + i] = a;
        }
        gridBarrier();
    }

    // ---- final squash (iter-2 norms are in buffer 0)
    gridBarrier();
    if (x == 0) {
        float nn = 0.f;
        #pragma unroll
        for (int t = 0; t < Jn * 3; t++) nn += __ldcg(&g_nPart[0][b * Jn * 3 + t]);
        kb_sh[0] = squash_k(nn);
    }
    __syncthreads();
    out[(size_t)bj * Xn + xg] = kb_sh[0] * s;
}

extern "C" void kernel_launch(void* const* d_in, const int* in_sizes, int n_in,
                              void* d_out, int out_size) {
    const float* u    = (const float*)d_in[0];
    const float* bias = (const float*)d_in[1];
    float* out = (float*)d_out;
    routing_all<<<GRIDG, NT>>>(u, bias, out);
}

// round 12
// speedup vs baseline: 1.5796x; 1.5796x over previous
#include <cuda_runtime.h>

// Shapes (fixed)
#define Bn 16
#define In 32
#define Cn 8
#define Jn 10
#define Dn 16
#define Xn 576   // D*H*W
#define XH 288   // half per CTA
#define NT 288
#define HWn 36
#define EPSf 1e-7f
#define GRIDH (Bn*Jn*2)   // 320 CTAs, entry = bj*2 + half

// Scratch (device globals). Partial entry layout: for batch b, its 20 entries
// are contiguous [b*20, b*20+20).
__device__ float g_U[(size_t)Bn*Jn*In*Xn];      // [bj][i][x], 11.8 MB (L2-resident)
__device__ float g_nPart1[GRIDH];               // iter-1 L1-norm partials
__device__ float g_aPart1[(size_t)GRIDH*In];    // iter-1 agreement [entry][i] (128B rows)
__device__ float g_nPart2[GRIDH];               // iter-2
__device__ float g_aPart2[(size_t)GRIDH*In];
__device__ float g_nPart3[GRIDH];               // iter-3 norms (for final squash)

__device__ __forceinline__ float squash_k(float n) {
    float n2 = n * n;
    return (n2 / (1.f + n2)) / (n + EPSf);
}

// Block sum over 288 threads (9 warps); valid on thread 0.
__device__ __forceinline__ float blockReduceSum288(float v) {
    __shared__ float red[9];
    int lane = threadIdx.x & 31, w = threadIdx.x >> 5;
    #pragma unroll
    for (int o = 16; o > 0; o >>= 1) v += __shfl_down_sync(0xffffffffu, v, o);
    if (lane == 0) red[w] = v;
    __syncthreads();
    float s = 0.f;
    if (threadIdx.x == 0) {
        #pragma unroll
        for (int k = 0; k < 9; k++) s += red[k];
    }
    return s;
}

// ---------------------------------------------------------------------------
// K1 (R6-measured ~14us @ 6.7TB/s): stream u_hat once (94 MB), write U to
// gmem (stays in L2), fuse iter-1 s / norm / agreement partials (c1 = 1/J).
// No barrier, no launch_bounds min -> free regs, pipelined waves.
__global__ void __launch_bounds__(NT) k_load(const float* __restrict__ u,
                                             const float* __restrict__ bias) {
    __shared__ __align__(16) float Us[In][XH];
    __shared__ float ss[XH];
    int bj = blockIdx.x >> 1, half = blockIdx.x & 1;
    int b = bj / Jn, j = bj % Jn;
    int x = threadIdx.x;
    int xg = half * XH + x;
    int w = x >> 5, lane = x & 31;

    int t4 = x % 72, g = x / 72;              // 4 i-groups x 72 float4-cols
    int xq = half * XH + t4 * 4;
    const float* base = u + (size_t)b * In * Cn * Jn * Xn + (size_t)j * Xn + xq;
    float* uout = &g_U[(size_t)bj * In * Xn + xq];
    #pragma unroll 2
    for (int ii = 0; ii < 8; ii++) {
        int i = g * 8 + ii;
        const float4* p = (const float4*)(base + (size_t)i * Cn * Jn * Xn);
        float4 a0 = __ldcs(p);
        float4 a1 = __ldcs(p + 1 * (Jn * Xn / 4));
        float4 a2 = __ldcs(p + 2 * (Jn * Xn / 4));
        float4 a3 = __ldcs(p + 3 * (Jn * Xn / 4));
        float4 a4 = __ldcs(p + 4 * (Jn * Xn / 4));
        float4 a5 = __ldcs(p + 5 * (Jn * Xn / 4));
        float4 a6 = __ldcs(p + 6 * (Jn * Xn / 4));
        float4 a7 = __ldcs(p + 7 * (Jn * Xn / 4));
        float4 acc;
        acc.x = ((a0.x + a1.x) + (a2.x + a3.x)) + ((a4.x + a5.x) + (a6.x + a7.x));
        acc.y = ((a0.y + a1.y) + (a2.y + a3.y)) + ((a4.y + a5.y) + (a6.y + a7.y));
        acc.z = ((a0.z + a1.z) + (a2.z + a3.z)) + ((a4.z + a5.z) + (a6.z + a7.z));
        acc.w = ((a0.w + a1.w) + (a2.w + a3.w)) + ((a4.w + a5.w) + (a6.w + a7.w));
        *(float4*)&Us[i][t4 * 4] = acc;
        *(float4*)(uout + (size_t)i * Xn) = acc;   // plain store -> L2
    }
    __syncthreads();

    float acc = 0.f;
    #pragma unroll
    for (int i = 0; i < In; i++) acc += Us[i][x];
    float s = acc * (1.0f / Jn) + bias[j * Dn + xg / HWn];

    float n = blockReduceSum288(fabsf(s));
    if (x == 0) g_nPart1[blockIdx.x] = n;

    ss[x] = s;
    __syncthreads();
    if (w < 8) {
        #pragma unroll
        for (int ii = 0; ii < 4; ii++) {
            int i = w * 4 + ii;
            float a = 0.f;
            #pragma unroll
            for (int xx = lane; xx < XH; xx += 32) a += Us[i][xx] * ss[xx];
            #pragma unroll
            for (int o = 16; o > 0; o >>= 1) a += __shfl_down_sync(0xffffffffu, a, o);
            if (lane == 0) g_aPart1[(size_t)blockIdx.x * In + i] = a;
        }
    }
}

// Shared head+body for K2/K3 expressed via a template-free helper pattern:
// (kept inline in each kernel for register freedom)

// ---------------------------------------------------------------------------
// K2: iteration 2. cp.async the U tile (L2-hot) while computing kb1/c2
// redundantly per CTA; then s2 / norm2 / agreement2 partials. No syncs.
__global__ void __launch_bounds__(NT) k_iter2(const float* __restrict__ bias) {
    __shared__ __align__(16) float Us[In][XH];
    __shared__ float ss[XH];
    __shared__ float sb[In * Jn];
    __shared__ float cs[In];
    __shared__ float kb_sh[Bn];
    int bj = blockIdx.x >> 1, half = blockIdx.x & 1;
    int j = bj % Jn;
    int x = threadIdx.x;
    int xg = half * XH + x;
    int w = x >> 5, lane = x & 31;
    int t4 = x % 72, g = x / 72;

    // fire U-tile copy: 8 x 16B cp.async per thread (rows 4k+g, col t4)
    {
        unsigned sbase = (unsigned)__cvta_generic_to_shared(&Us[0][0]);
        const float* usrc = &g_U[(size_t)bj * In * Xn + half * XH + t4 * 4];
        #pragma unroll
        for (int k = 0; k < 8; k++) {
            int row = k * 4 + g;
            unsigned dst = sbase + (unsigned)(row * XH + t4 * 4) * 4u;
            const float* src = usrc + (size_t)row * Xn;
            asm volatile("cp.async.cg.shared.global [%0], [%1], 16;\n"
                         :: "r"(dst), "l"(src) : "memory");
        }
        asm volatile("cp.async.commit_group;\n" ::: "memory");
    }

    // head: kb1 + b_ij update 1 + softmax -> c2 (identical in every CTA)
    if (x < Bn) {
        float nn = 0.f;
        #pragma unroll
        for (int t = 0; t < Jn * 2; t++) nn += g_nPart1[x * Jn * 2 + t];
        kb_sh[x] = squash_k(nn);
    }
    __syncthreads();
    for (int jj = w; jj < Jn; jj += 9) {
        float a = 0.f;
        #pragma unroll
        for (int bb = 0; bb < Bn; bb++) {
            int e0 = (bb * Jn + jj) * 2;
            a += kb_sh[bb] * (g_aPart1[(size_t)e0 * In + lane]
                            + g_aPart1[(size_t)(e0 + 1) * In + lane]);
        }
        sb[lane * Jn + jj] = a;          // b_ij after update 1
    }
    __syncthreads();
    if (x < In) {
        float mx = -1e30f;
        #pragma unroll
        for (int jj = 0; jj < Jn; jj++) mx = fmaxf(mx, sb[x * Jn + jj]);
        float den = 0.f;
        #pragma unroll
        for (int jj = 0; jj < Jn; jj++) den += expf(sb[x * Jn + jj] - mx);
        cs[x] = expf(sb[x * Jn + j] - mx) / den;
    }
    asm volatile("cp.async.wait_group 0;\n" ::: "memory");
    __syncthreads();

    // s2 / norm2 / agreement2
    float acc = 0.f;
    #pragma unroll
    for (int i = 0; i < In; i++) acc += cs[i] * Us[i][x];
    float s = acc + bias[j * Dn + xg / HWn];

    float n = blockReduceSum288(fabsf(s));
    if (x == 0) g_nPart2[blockIdx.x] = n;

    ss[x] = s;
    __syncthreads();
    if (w < 8) {
        #pragma unroll
        for (int ii = 0; ii < 4; ii++) {
            int i = w * 4 + ii;
            float a = 0.f;
            #pragma unroll
            for (int xx = lane; xx < XH; xx += 32) a += Us[i][xx] * ss[xx];
            #pragma unroll
            for (int o = 16; o > 0; o >>= 1) a += __shfl_down_sync(0xffffffffu, a, o);
            if (lane == 0) g_aPart2[(size_t)blockIdx.x * In + i] = a;
        }
    }
}

// ---------------------------------------------------------------------------
// K3: iteration 3. b_ij = update1 + update2; s3 -> d_out (unscaled); norm3.
__global__ void __launch_bounds__(NT) k_iter3(const float* __restrict__ bias,
                                              float* __restrict__ out) {
    __shared__ __align__(16) float Us[In][XH];
    __shared__ float sb[In * Jn];
    __shared__ float cs[In];
    __shared__ float kb1_sh[Bn];
    __shared__ float kb2_sh[Bn];
    int bj = blockIdx.x >> 1, half = blockIdx.x & 1;
    int j = bj % Jn;
    int x = threadIdx.x;
    int xg = half * XH + x;
    int w = x >> 5, lane = x & 31;
    int t4 = x % 72, g = x / 72;

    {
        unsigned sbase = (unsigned)__cvta_generic_to_shared(&Us[0][0]);
        const float* usrc = &g_U[(size_t)bj * In * Xn + half * XH + t4 * 4];
        #pragma unroll
        for (int k = 0; k < 8; k++) {
            int row = k * 4 + g;
            unsigned dst = sbase + (unsigned)(row * XH + t4 * 4) * 4u;
            const float* src = usrc + (size_t)row * Xn;
            asm volatile("cp.async.cg.shared.global [%0], [%1], 16;\n"
                         :: "r"(dst), "l"(src) : "memory");
        }
        asm volatile("cp.async.commit_group;\n" ::: "memory");
    }

    if (x < Bn) {
        float n1 = 0.f, n2 = 0.f;
        #pragma unroll
        for (int t = 0; t < Jn * 2; t++) {
            n1 += g_nPart1[x * Jn * 2 + t];
            n2 += g_nPart2[x * Jn * 2 + t];
        }
        kb1_sh[x] = squash_k(n1);
        kb2_sh[x] = squash_k(n2);
    }
    __syncthreads();
    for (int jj = w; jj < Jn; jj += 9) {
        float a = 0.f;
        #pragma unroll
        for (int bb = 0; bb < Bn; bb++) {
            int e0 = (bb * Jn + jj) * 2;
            a += kb1_sh[bb] * (g_aPart1[(size_t)e0 * In + lane]
                             + g_aPart1[(size_t)(e0 + 1) * In + lane]);
            a += kb2_sh[bb] * (g_aPart2[(size_t)e0 * In + lane]
                             + g_aPart2[(size_t)(e0 + 1) * In + lane]);
        }
        sb[lane * Jn + jj] = a;          // b_ij after updates 1+2
    }
    __syncthreads();
    if (x < In) {
        float mx = -1e30f;
        #pragma unroll
        for (int jj = 0; jj < Jn; jj++) mx = fmaxf(mx, sb[x * Jn + jj]);
        float den = 0.f;
        #pragma unroll
        for (int jj = 0; jj < Jn; jj++) den += expf(sb[x * Jn + jj] - mx);
        cs[x] = expf(sb[x * Jn + j] - mx) / den;
    }
    asm volatile("cp.async.wait_group 0;\n" ::: "memory");
    __syncthreads();

    float acc = 0.f;
    #pragma unroll
    for (int i = 0; i < In; i++) acc += cs[i] * Us[i][x];
    float s = acc + bias[j * Dn + xg / HWn];

    float n = blockReduceSum288(fabsf(s));
    if (x == 0) g_nPart3[blockIdx.x] = n;

    out[(size_t)bj * Xn + xg] = s;       // unscaled; K4 scales in place
}

// ---------------------------------------------------------------------------
// K4: in-place squash scaling of d_out. Deterministic & replay-idempotent
// (K3 rewrites s3 before every K4 in each graph replay).
__global__ void __launch_bounds__(NT) k_scale(float* __restrict__ out) {
    __shared__ float kb_sh;
    int bj = blockIdx.x >> 1, half = blockIdx.x & 1;
    int b = bj / Jn;
    int x = threadIdx.x;
    // lanes 0..19 of warp 0 load the 20 norm partials of batch b, reduce
    if (threadIdx.x < 32) {
        float v = (x < Jn * 2) ? g_nPart3[b * Jn * 2 + x] : 0.f;
        #pragma unroll
        for (int o = 16; o > 0; o >>= 1) v += __shfl_down_sync(0xffffffffu, v, o);
        if (x == 0) kb_sh = squash_k(v);
    }
    __syncthreads();
    size_t idx = (size_t)bj * Xn + half * XH + x;
    out[idx] = kb_sh * out[idx];
}

extern "C" void kernel_launch(void* const* d_in, const int* in_sizes, int n_in,
                              void* d_out, int out_size) {
    const float* u    = (const float*)d_in[0];
    const float* bias = (const float*)d_in[1];
    float* out = (float*)d_out;
    k_load <<<GRIDH, NT>>>(u, bias);
    k_iter2<<<GRIDH, NT>>>(bias);
    k_iter3<<<GRIDH, NT>>>(bias, out);
    k_scale<<<GRIDH, NT>>>(out);
}